// round 10
// baseline (speedup 1.0000x reference)
#include <cuda_runtime.h>

// Warping_65094524339056 — Round 10: 16x16x32 tile (halo amortization) +
// LDG.64 ddf fetch (9->6 wavefronts) + depth-4 ring + 64-reg budget.

#define DMASK 127
#define H    4
#define EX   25
#define EY   25
#define EZV  41
#define SZ   41                  // odd stride: bank spread
#define SXY  (EY*SZ)             // 1025
#define TILE_ELEMS (EX*SXY)      // 25625 floats = 102.5 KB
#define NROWS (EX*EY)            // 625
#define BLOCK 512
#define VPT   16
#define PF    4                  // prefetch depth

__device__ __forceinline__ float clampf(float v) {
    return fminf(fmaxf(v, 0.0f), 127.0f);
}

__global__ __launch_bounds__(BLOCK, 2) void warp_kernel(
    const float* __restrict__ ddf,
    const float* __restrict__ image,
    float* __restrict__ out)
{
    extern __shared__ float tile[];

    int tid = threadIdx.x;
    int bid = blockIdx.x;
    // 8(x) x 8(y) x 4(z) tiles x 4 batches = 1024 blocks
    int tz = bid & 3;
    int ty = (bid >> 2) & 7;
    int tx = (bid >> 5) & 7;
    int b  = bid >> 8;

    int X0 = tx << 4;
    int Y0 = ty << 4;
    int Z0 = tz << 5;

    const float* img = image + ((long long)b << 21);

    // ---- stage tile: one row per warp per step; clamps warp-uniform ----
    {
        int wid  = tid >> 5;
        int lane = tid & 31;
        for (int r = wid; r < NROWS; r += 16) {
            int sy = r % EY;
            int sx = r / EY;
            int gx = min(max(X0 - H + sx, 0), DMASK);
            int gy = min(max(Y0 - H + sy, 0), DMASK);
            const float* rowp = img + (gx << 14) + (gy << 7);
            float* srow = tile + r * SZ;
            int gz0 = max(Z0 - H + lane, 0);
            srow[lane] = __ldg(rowp + gz0);
            if (lane < EZV - 32) {
                int gz1 = min(Z0 - H + 32 + lane, DMASK);
                srow[lane + 32] = __ldg(rowp + gz1);
            }
        }
    }
    __syncthreads();

    // ---- compute: 16 voxels/thread (x = X0 + v); lanes z-consecutive ----
    int lz = tid & 31;
    int ly = tid >> 5;                 // 0..15

    int y = Y0 + ly;
    int z = Z0 + lz;

    int vid0 = (X0 << 14) + (y << 7) + z;
    const float* ddfb = ddf + ((long long)b << 21) * 3;
    float*       outb = out + ((long long)b << 21);

    // ddf fetch: lane-parity-aligned LDG.64 + scalar.
    // vid0*3 parity == lz parity. even lane: f2@off -> (dx,dy), s@off+2 -> dz
    //                             odd  lane: f2@off+1 -> (dy,dz), s@off -> dx
    int odd = lz & 1;
    const float* dp0 = ddfb + (long long)vid0 * 3;
    const float2* dpa0 = (const float2*)(dp0 + odd);       // even-aligned
    const float*  dps0 = dp0 + (odd ? 0 : 2);
    const int DSTRIDE2 = (3 << 14) / 2;  // float2 elems per x+=1 step
    const int DSTRIDE  = 3 << 14;

    const float yf = (float)y;
    const float zf = (float)z;
    const int ox = X0 - H, oy = Y0 - H, oz = Z0 - H;

    // ---- prefetch ring (depth PF) ----
    float2 ra[PF];
    float  rs[PF];
#pragma unroll
    for (int p = 0; p < PF; p++) {
        ra[p] = __ldcs(dpa0 + p * DSTRIDE2);
        rs[p] = __ldcs(dps0 + p * DSTRIDE);
    }

#pragma unroll
    for (int v = 0; v < VPT; v++) {
        int slot = v % PF;
        float2 a = ra[slot];
        float  s = rs[slot];
        float dx = odd ? s   : a.x;
        float dy = odd ? a.x : a.y;
        float dz = odd ? a.y : s;

        if (v + PF < VPT) {
            ra[slot] = __ldcs(dpa0 + (v + PF) * DSTRIDE2);
            rs[slot] = __ldcs(dps0 + (v + PF) * DSTRIDE);
        }

        int vid = vid0 + (v << 14);

        float fx = (float)(X0 + v) + dx;     // same fp as reference
        float fy = yf + dy;
        float fz = zf + dz;

        int ix0 = __float2int_rd(fx);
        int iy0 = __float2int_rd(fy);
        int iz0 = __float2int_rd(fz);
        float wx = fx - (float)ix0;
        float wy = fy - (float)iy0;
        float wz = fz - (float)iz0;

        int sx0 = ix0 - ox;
        int sy0 = iy0 - oy;
        int sz0 = iz0 - oz;

        bool ok = ((unsigned)sx0 <= (unsigned)(EX - 2)) &
                  ((unsigned)sy0 <= (unsigned)(EY - 2)) &
                  ((unsigned)sz0 <= (unsigned)(EZV - 2));

        float v000, v001, v010, v011, v100, v101, v110, v111;
        if (ok) {
            int base = (sx0 * EY + sy0) * SZ + sz0;
            v000 = tile[base];
            v001 = tile[base + 1];
            v010 = tile[base + SZ];
            v011 = tile[base + SZ + 1];
            v100 = tile[base + SXY];
            v101 = tile[base + SXY + 1];
            v110 = tile[base + SXY + SZ];
            v111 = tile[base + SXY + SZ + 1];
        } else {
            // rare: beyond halo -> clamped global gather (matches reference)
            float cfx = clampf(fx), cfy = clampf(fy), cfz = clampf(fz);
            ix0 = (int)cfx;  iy0 = (int)cfy;  iz0 = (int)cfz;
            wx = cfx - (float)ix0;
            wy = cfy - (float)iy0;
            wz = cfz - (float)iz0;
            int ix1 = min(ix0 + 1, DMASK);
            int iy1 = min(iy0 + 1, DMASK);
            int iz1 = min(iz0 + 1, DMASK);
            int g00 = (ix0 << 14) + (iy0 << 7);
            int g01 = (ix0 << 14) + (iy1 << 7);
            int g10 = (ix1 << 14) + (iy0 << 7);
            int g11 = (ix1 << 14) + (iy1 << 7);
            v000 = __ldg(img + g00 + iz0);  v001 = __ldg(img + g00 + iz1);
            v010 = __ldg(img + g01 + iz0);  v011 = __ldg(img + g01 + iz1);
            v100 = __ldg(img + g10 + iz0);  v101 = __ldg(img + g10 + iz1);
            v110 = __ldg(img + g11 + iz0);  v111 = __ldg(img + g11 + iz1);
        }

        float c00 = v000 + wz * (v001 - v000);
        float c01 = v010 + wz * (v011 - v010);
        float c10 = v100 + wz * (v101 - v100);
        float c11 = v110 + wz * (v111 - v110);
        float c0  = c00 + wy * (c01 - c00);
        float c1  = c10 + wy * (c11 - c10);
        __stcs(&outb[vid], c0 + wx * (c1 - c0));
    }
}

extern "C" void kernel_launch(void* const* d_in, const int* in_sizes, int n_in,
                              void* d_out, int out_size)
{
    const float* ddf   = (const float*)d_in[0];
    const float* image = (const float*)d_in[1];
    float* out = (float*)d_out;

    size_t smem = TILE_ELEMS * sizeof(float);   // 102500 B
    cudaFuncSetAttribute(warp_kernel,
                         cudaFuncAttributeMaxDynamicSharedMemorySize, (int)smem);

    warp_kernel<<<1024, BLOCK, smem>>>(ddf, image, out);
}

// round 11
// speedup vs baseline: 1.2376x; 1.2376x over previous
#include <cuda_runtime.h>

// Warping_65094524339056 — Round 11: R9 geometry (48 warps/SM, depth-3 ring)
// + float4 tile staging + ddf prefetch hidden behind the staging barrier.
//
// Staging: each (sx,sy) row's z-window is fetched as aligned LDG.128:
//   tz=1,2: 11 vecs from gz=Z0-4  -> slots 0..43   (covers gz Z0-4..Z0+39)
//   tz=0:   10 vecs from gz=0     -> slots 4..43   (slots 0..3 fixed up = img[0])
//   tz=3:    9 vecs from gz=92    -> slots 0..35   (slots 36..40 fixed up = img[127])
// x/y border clamp handled per-row as before (duplicated rows).

#define DMASK 127
#define H    4
#define EX   25
#define EY   17
#define EZV  41
#define SZ   44                  // row stride (holds 11 float4)
#define SXY  (EY*SZ)             // 748
#define TILE_ELEMS (EX*SXY)      // 18700 floats = 74.8 KB
#define NROWS (EX*EY)            // 425
#define BLOCK 512
#define VPT   8
#define PF    3                  // prefetch depth

__device__ __forceinline__ float clampf(float v) {
    return fminf(fmaxf(v, 0.0f), 127.0f);
}

__global__ __launch_bounds__(BLOCK, 3) void warp_kernel(
    const float* __restrict__ ddf,
    const float* __restrict__ image,
    float* __restrict__ out)
{
    extern __shared__ float tile[];

    int tid = threadIdx.x;
    int bid = blockIdx.x;
    // 8(x) x 16(y) x 4(z) tiles x 4 batches = 2048 blocks
    int tz = bid & 3;
    int ty = (bid >> 2) & 15;
    int tx = (bid >> 6) & 7;
    int b  = bid >> 9;

    int X0 = tx << 4;
    int Y0 = ty << 3;
    int Z0 = tz << 5;

    const float* img = image + ((long long)b << 21);

    // ---- per-thread compute coords (needed early for ddf prefetch) ----
    int lz  = tid & 31;
    int ly  = (tid >> 5) & 7;
    int lxh = tid >> 8;                // 0/1; x = X0 + lxh + 2*v
    int y = Y0 + ly;
    int z = Z0 + lz;
    int xb = X0 + lxh;

    int vid0 = (xb << 14) + (y << 7) + z;
    const float* ddfb = ddf + ((long long)b << 21) * 3;
    float*       outb = out + ((long long)b << 21);
    const float* dp0  = ddfb + (long long)vid0 * 3;
    const int DSTRIDE = 3 << 15;       // ddf elems per x+=2 step

    // ---- stage tile with float4 loads ----
    {
        int K, gzs, szs;
        if (tz == 0)      { K = 10; gzs = 0;      szs = 4; }
        else if (tz == 3) { K = 9;  gzs = Z0 - 4; szs = 0; }
        else              { K = 11; gzs = Z0 - 4; szs = 0; }

        const int NOPS = NROWS * 11;
        for (int i = tid; i < NOPS; i += BLOCK) {
            int r = i / 11;
            int j = i - r * 11;
            if (j < K) {
                int sy = r % EY;
                int sx = r / EY;
                int gx = min(max(X0 - H + sx, 0), DMASK);
                int gy = min(max(Y0 - H + sy, 0), DMASK);
                const float4* src =
                    (const float4*)(img + (gx << 14) + (gy << 7) + gzs) + j;
                float4 val = __ldg(src);
                *((float4*)(tile + r * SZ + szs) + j) = val;
            }
        }
    }

    // ---- ddf prefetch ring: issue BEFORE the barrier (latency hidden) ----
    float rdx[PF], rdy[PF], rdz[PF];
#pragma unroll
    for (int p = 0; p < PF; p++) {
        const float* pp = dp0 + p * DSTRIDE;
        rdx[p] = __ldcs(pp);
        rdy[p] = __ldcs(pp + 1);
        rdz[p] = __ldcs(pp + 2);
    }

    __syncthreads();

    // ---- border-z fixup (block-uniform branch) ----
    if (tz == 0) {
        for (int r = tid; r < NROWS; r += BLOCK) {
            float v = tile[r * SZ + 4];           // img[...,0]
            tile[r * SZ + 0] = v;
            tile[r * SZ + 1] = v;
            tile[r * SZ + 2] = v;
            tile[r * SZ + 3] = v;
        }
        __syncthreads();
    } else if (tz == 3) {
        for (int r = tid; r < NROWS; r += BLOCK) {
            float v = tile[r * SZ + 35];          // img[...,127]
            tile[r * SZ + 36] = v;
            tile[r * SZ + 37] = v;
            tile[r * SZ + 38] = v;
            tile[r * SZ + 39] = v;
            tile[r * SZ + 40] = v;
        }
        __syncthreads();
    }

    const float yf = (float)y;
    const float zf = (float)z;
    const int ox = X0 - H, oy = Y0 - H, oz = Z0 - H;

#pragma unroll
    for (int v = 0; v < VPT; v++) {
        int slot = v % PF;
        float dx = rdx[slot], dy = rdy[slot], dz = rdz[slot];

        if (v + PF < VPT) {
            const float* pn = dp0 + (v + PF) * DSTRIDE;
            rdx[slot] = __ldcs(pn);
            rdy[slot] = __ldcs(pn + 1);
            rdz[slot] = __ldcs(pn + 2);
        }

        int vid = vid0 + (v << 15);

        float fx = (float)(xb + 2 * v) + dx;     // same fp as reference
        float fy = yf + dy;
        float fz = zf + dz;

        int ix0 = __float2int_rd(fx);
        int iy0 = __float2int_rd(fy);
        int iz0 = __float2int_rd(fz);
        float wx = fx - (float)ix0;
        float wy = fy - (float)iy0;
        float wz = fz - (float)iz0;

        int sx0 = ix0 - ox;
        int sy0 = iy0 - oy;
        int sz0 = iz0 - oz;

        bool ok = ((unsigned)sx0 <= (unsigned)(EX - 2)) &
                  ((unsigned)sy0 <= (unsigned)(EY - 2)) &
                  ((unsigned)sz0 <= (unsigned)(EZV - 2));

        float v000, v001, v010, v011, v100, v101, v110, v111;
        if (ok) {
            int base = (sx0 * EY + sy0) * SZ + sz0;
            v000 = tile[base];
            v001 = tile[base + 1];
            v010 = tile[base + SZ];
            v011 = tile[base + SZ + 1];
            v100 = tile[base + SXY];
            v101 = tile[base + SXY + 1];
            v110 = tile[base + SXY + SZ];
            v111 = tile[base + SXY + SZ + 1];
        } else {
            // rare: beyond halo -> clamped global gather (matches reference)
            float cfx = clampf(fx), cfy = clampf(fy), cfz = clampf(fz);
            ix0 = (int)cfx;  iy0 = (int)cfy;  iz0 = (int)cfz;
            wx = cfx - (float)ix0;
            wy = cfy - (float)iy0;
            wz = cfz - (float)iz0;
            int ix1 = min(ix0 + 1, DMASK);
            int iy1 = min(iy0 + 1, DMASK);
            int iz1 = min(iz0 + 1, DMASK);
            int g00 = (ix0 << 14) + (iy0 << 7);
            int g01 = (ix0 << 14) + (iy1 << 7);
            int g10 = (ix1 << 14) + (iy0 << 7);
            int g11 = (ix1 << 14) + (iy1 << 7);
            v000 = __ldg(img + g00 + iz0);  v001 = __ldg(img + g00 + iz1);
            v010 = __ldg(img + g01 + iz0);  v011 = __ldg(img + g01 + iz1);
            v100 = __ldg(img + g10 + iz0);  v101 = __ldg(img + g10 + iz1);
            v110 = __ldg(img + g11 + iz0);  v111 = __ldg(img + g11 + iz1);
        }

        float c00 = v000 + wz * (v001 - v000);
        float c01 = v010 + wz * (v011 - v010);
        float c10 = v100 + wz * (v101 - v100);
        float c11 = v110 + wz * (v111 - v110);
        float c0  = c00 + wy * (c01 - c00);
        float c1  = c10 + wy * (c11 - c10);
        __stcs(&outb[vid], c0 + wx * (c1 - c0));
    }
}

extern "C" void kernel_launch(void* const* d_in, const int* in_sizes, int n_in,
                              void* d_out, int out_size)
{
    const float* ddf   = (const float*)d_in[0];
    const float* image = (const float*)d_in[1];
    float* out = (float*)d_out;

    size_t smem = TILE_ELEMS * sizeof(float);   // 74800 B
    cudaFuncSetAttribute(warp_kernel,
                         cudaFuncAttributeMaxDynamicSharedMemorySize, (int)smem);

    warp_kernel<<<2048, BLOCK, smem>>>(ddf, image, out);
}

// round 12
// speedup vs baseline: 1.5382x; 1.2429x over previous
#include <cuda.h>
#include <cuda_runtime.h>

// Warping_65094524339056 — Round 12: TMA tile staging (L2->SMEM, zero L1
// wavefronts for staging) + R11 compute path.
//
// Tile per 512-thread block: image box (z=44, y=17, x=25) = 74800 B, loaded
// by ONE cp.async.bulk.tensor.4d. OOB regions are zero-filled by TMA and
// fixed up by border blocks via SMEM->SMEM edge duplication (x->y->z order).
// Compute: clamp-free trilinear fast path on the tile; rare out-of-halo
// voxels use the clamped global path. ddf via depth-3 __ldcs prefetch ring
// issued before the TMA wait.

#define DMASK 127
#define H    4
#define EX   25
#define EY   17
#define EZV  41                  // valid z slots (used by ok-test)
#define SZ   44                  // TMA box z = 44 floats = 176 B (16B mult.)
#define SXY  (EY*SZ)             // 748
#define TILE_ELEMS (EX*SXY)      // 18700 floats = 74800 B
#define NROWS (EX*EY)            // 425
#define TILE_BYTES (TILE_ELEMS*4)
#define BLOCK 512
#define VPT   8
#define PF    3

__device__ __forceinline__ float clampf(float v) {
    return fminf(fmaxf(v, 0.0f), 127.0f);
}

__device__ __forceinline__ unsigned smem_u32(const void* p) {
    unsigned a;
    asm("{ .reg .u64 t; cvta.to.shared.u64 t, %1; cvt.u32.u64 %0, t; }"
        : "=r"(a) : "l"(p));
    return a;
}

__global__ __launch_bounds__(BLOCK, 3) void warp_kernel(
    const float* __restrict__ ddf,
    const float* __restrict__ image,
    float* __restrict__ out,
    const __grid_constant__ CUtensorMap desc)
{
    extern __shared__ float tile[];
    // mbarrier lives after the tile (74800 is 8B-aligned)
    unsigned sbase = smem_u32(tile);
    unsigned mbar  = sbase + TILE_BYTES;

    int tid = threadIdx.x;
    int bid = blockIdx.x;
    // 8(x) x 16(y) x 4(z) tiles x 4 batches = 2048 blocks
    int tz = bid & 3;
    int ty = (bid >> 2) & 15;
    int tx = (bid >> 6) & 7;
    int b  = bid >> 9;

    int X0 = tx << 4;
    int Y0 = ty << 3;
    int Z0 = tz << 5;

    const float* img = image + ((long long)b << 21);

    // ---- per-thread compute coords ----
    int lz  = tid & 31;
    int ly  = (tid >> 5) & 7;
    int lxh = tid >> 8;                // 0/1; x = X0 + lxh + 2*v
    int y = Y0 + ly;
    int z = Z0 + lz;
    int xb = X0 + lxh;

    int vid0 = (xb << 14) + (y << 7) + z;
    const float* ddfb = ddf + ((long long)b << 21) * 3;
    float*       outb = out + ((long long)b << 21);
    const float* dp0  = ddfb + (long long)vid0 * 3;
    const int DSTRIDE = 3 << 15;

    if (tid == 0) {
        asm volatile("mbarrier.init.shared.b64 [%0], %1;"
                     :: "r"(mbar), "r"(1u) : "memory");
    }

    // ---- ddf prefetch ring: in flight while TMA runs ----
    float rdx[PF], rdy[PF], rdz[PF];
#pragma unroll
    for (int p = 0; p < PF; p++) {
        const float* pp = dp0 + p * DSTRIDE;
        rdx[p] = __ldcs(pp);
        rdy[p] = __ldcs(pp + 1);
        rdz[p] = __ldcs(pp + 2);
    }

    __syncthreads();   // mbarrier init visible

    if (tid == 0) {
        asm volatile("mbarrier.arrive.expect_tx.shared.b64 _, [%0], %1;"
                     :: "r"(mbar), "r"((unsigned)TILE_BYTES) : "memory");
        asm volatile(
            "cp.async.bulk.tensor.4d.shared::cta.global.tile.mbarrier::complete_tx::bytes "
            "[%0], [%1, {%2, %3, %4, %5}], [%6];"
            :: "r"(sbase), "l"(&desc),
               "r"(Z0 - H), "r"(Y0 - H), "r"(X0 - H), "r"(b),
               "r"(mbar)
            : "memory");
    }

    // ---- wait for the tile ----
    asm volatile(
        "{\n\t.reg .pred P;\n\t"
        "W_%=:\n\t"
        "mbarrier.try_wait.parity.shared.b64 P, [%0], %1;\n\t"
        "@!P bra W_%=;\n\t}"
        :: "r"(mbar), "r"(0u) : "memory");

    // ---- border fixups (block-uniform; TMA zero-filled OOB -> duplicate
    //      clamped edges; order x -> y -> z propagates corners) ----
    if (tx == 0) {          // gx<0: planes sx=0..3 <- sx=4
        for (int i = tid; i < 4 * SXY; i += BLOCK)
            tile[i] = tile[4 * SXY + (i % SXY)];
        __syncthreads();
    } else if (tx == 7) {   // gx>127: planes sx=20..24 <- sx=19
        for (int i = tid; i < 5 * SXY; i += BLOCK)
            tile[20 * SXY + i] = tile[19 * SXY + (i % SXY)];
        __syncthreads();
    }
    if (ty == 0) {          // gy<0: rows sy=0..3 <- sy=4, every sx plane
        for (int i = tid; i < EX * 4 * SZ; i += BLOCK) {
            int sx  = i / (4 * SZ);
            int rem = i - sx * (4 * SZ);
            tile[sx * SXY + rem] = tile[sx * SXY + 4 * SZ + (rem % SZ)];
        }
        __syncthreads();
    } else if (ty == 15) {  // gy>127: rows sy=12..16 <- sy=11
        for (int i = tid; i < EX * 5 * SZ; i += BLOCK) {
            int sx  = i / (5 * SZ);
            int rem = i - sx * (5 * SZ);
            tile[sx * SXY + 12 * SZ + rem] = tile[sx * SXY + 11 * SZ + (rem % SZ)];
        }
        __syncthreads();
    }
    if (tz == 0) {          // gz<0: slots 0..3 <- slot 4, every row
        for (int r = tid; r < NROWS; r += BLOCK) {
            float v = tile[r * SZ + 4];
            tile[r * SZ + 0] = v;  tile[r * SZ + 1] = v;
            tile[r * SZ + 2] = v;  tile[r * SZ + 3] = v;
        }
        __syncthreads();
    } else if (tz == 3) {   // gz>127: slots 36..40 <- slot 35
        for (int r = tid; r < NROWS; r += BLOCK) {
            float v = tile[r * SZ + 35];
            tile[r * SZ + 36] = v;  tile[r * SZ + 37] = v;
            tile[r * SZ + 38] = v;  tile[r * SZ + 39] = v;
            tile[r * SZ + 40] = v;
        }
        __syncthreads();
    }

    const float yf = (float)y;
    const float zf = (float)z;
    const int ox = X0 - H, oy = Y0 - H, oz = Z0 - H;

#pragma unroll
    for (int v = 0; v < VPT; v++) {
        int slot = v % PF;
        float dx = rdx[slot], dy = rdy[slot], dz = rdz[slot];

        if (v + PF < VPT) {
            const float* pn = dp0 + (v + PF) * DSTRIDE;
            rdx[slot] = __ldcs(pn);
            rdy[slot] = __ldcs(pn + 1);
            rdz[slot] = __ldcs(pn + 2);
        }

        int vid = vid0 + (v << 15);

        float fx = (float)(xb + 2 * v) + dx;     // same fp as reference
        float fy = yf + dy;
        float fz = zf + dz;

        int ix0 = __float2int_rd(fx);
        int iy0 = __float2int_rd(fy);
        int iz0 = __float2int_rd(fz);
        float wx = fx - (float)ix0;
        float wy = fy - (float)iy0;
        float wz = fz - (float)iz0;

        int sx0 = ix0 - ox;
        int sy0 = iy0 - oy;
        int sz0 = iz0 - oz;

        bool ok = ((unsigned)sx0 <= (unsigned)(EX - 2)) &
                  ((unsigned)sy0 <= (unsigned)(EY - 2)) &
                  ((unsigned)sz0 <= (unsigned)(EZV - 2));

        float v000, v001, v010, v011, v100, v101, v110, v111;
        if (ok) {
            int base = (sx0 * EY + sy0) * SZ + sz0;
            v000 = tile[base];
            v001 = tile[base + 1];
            v010 = tile[base + SZ];
            v011 = tile[base + SZ + 1];
            v100 = tile[base + SXY];
            v101 = tile[base + SXY + 1];
            v110 = tile[base + SXY + SZ];
            v111 = tile[base + SXY + SZ + 1];
        } else {
            // rare: beyond halo -> clamped global gather (matches reference)
            float cfx = clampf(fx), cfy = clampf(fy), cfz = clampf(fz);
            ix0 = (int)cfx;  iy0 = (int)cfy;  iz0 = (int)cfz;
            wx = cfx - (float)ix0;
            wy = cfy - (float)iy0;
            wz = cfz - (float)iz0;
            int ix1 = min(ix0 + 1, DMASK);
            int iy1 = min(iy0 + 1, DMASK);
            int iz1 = min(iz0 + 1, DMASK);
            int g00 = (ix0 << 14) + (iy0 << 7);
            int g01 = (ix0 << 14) + (iy1 << 7);
            int g10 = (ix1 << 14) + (iy0 << 7);
            int g11 = (ix1 << 14) + (iy1 << 7);
            v000 = __ldg(img + g00 + iz0);  v001 = __ldg(img + g00 + iz1);
            v010 = __ldg(img + g01 + iz0);  v011 = __ldg(img + g01 + iz1);
            v100 = __ldg(img + g10 + iz0);  v101 = __ldg(img + g10 + iz1);
            v110 = __ldg(img + g11 + iz0);  v111 = __ldg(img + g11 + iz1);
        }

        float c00 = v000 + wz * (v001 - v000);
        float c01 = v010 + wz * (v011 - v010);
        float c10 = v100 + wz * (v101 - v100);
        float c11 = v110 + wz * (v111 - v110);
        float c0  = c00 + wy * (c01 - c00);
        float c1  = c10 + wy * (c11 - c10);
        __stcs(&outb[vid], c0 + wx * (c1 - c0));
    }
}

typedef CUresult (*EncodeTiledFn)(
    CUtensorMap*, CUtensorMapDataType, cuuint32_t, void*,
    const cuuint64_t*, const cuuint64_t*, const cuuint32_t*, const cuuint32_t*,
    CUtensorMapInterleave, CUtensorMapSwizzle, CUtensorMapL2promotion,
    CUtensorMapFloatOOBfill);

extern "C" void kernel_launch(void* const* d_in, const int* in_sizes, int n_in,
                              void* d_out, int out_size)
{
    const float* ddf   = (const float*)d_in[0];
    const float* image = (const float*)d_in[1];
    float* out = (float*)d_out;

    // Driver entry point via runtime API (no -lcuda needed)
    void* fp = nullptr;
    cudaDriverEntryPointQueryResult qres;
    cudaGetDriverEntryPoint("cuTensorMapEncodeTiled", &fp,
                            cudaEnableDefault, &qres);
    EncodeTiledFn encode = (EncodeTiledFn)fp;

    // 4D map over image: (z=128, y=128, x=128, b=4); box (44,17,25,1)
    CUtensorMap desc;
    cuuint64_t dims[4]    = {128, 128, 128, 4};
    cuuint64_t strides[3] = {128ull * 4, 128ull * 128 * 4,
                             128ull * 128 * 128 * 4};
    cuuint32_t box[4]     = {SZ, EY, EX, 1};
    cuuint32_t estr[4]    = {1, 1, 1, 1};
    encode(&desc, CU_TENSOR_MAP_DATA_TYPE_FLOAT32, 4, (void*)image,
           dims, strides, box, estr,
           CU_TENSOR_MAP_INTERLEAVE_NONE, CU_TENSOR_MAP_SWIZZLE_NONE,
           CU_TENSOR_MAP_L2_PROMOTION_L2_128B,
           CU_TENSOR_MAP_FLOAT_OOB_FILL_NONE);

    size_t smem = TILE_BYTES + 16;              // tile + mbarrier
    cudaFuncSetAttribute(warp_kernel,
                         cudaFuncAttributeMaxDynamicSharedMemorySize, (int)smem);

    warp_kernel<<<2048, BLOCK, smem>>>(ddf, image, out, desc);
}